// round 6
// baseline (speedup 1.0000x reference)
#include <cuda_runtime.h>
#include <cuda_bf16.h>
#include <cstddef>

#define D_IN   128
#define D_OUT  128
#define D_EDGE 32
#define MAX_NODES 100000

// Scratch: per-node precomputed (X_src @ W_src + b) for each relation.
__device__ float g_xwu[(size_t)MAX_NODES * D_OUT];
__device__ float g_xwi[(size_t)MAX_NODES * D_OUT];

// ---------------------------------------------------------------------------
// Packed f32x2 helpers. X operands come from smem ALREADY duplicated, so the
// inner loops contain no splat MOVs at all.
// ---------------------------------------------------------------------------
__device__ __forceinline__ unsigned long long fma2(unsigned long long a,
                                                   unsigned long long b,
                                                   unsigned long long c) {
    unsigned long long d;
    asm("fma.rn.f32x2 %0, %1, %2, %3;" : "=l"(d) : "l"(a), "l"(b), "l"(c));
    return d;
}

union F4U2 { float4 f; ulonglong2 u; };

__device__ __forceinline__ void red_add_v4(float* p, float4 v) {
    asm volatile("red.global.add.v4.f32 [%0], {%1,%2,%3,%4};"
                 :: "l"(p), "f"(v.x), "f"(v.y), "f"(v.z), "f"(v.w)
                 : "memory");
}

// dup-expand one float4 (a,b,c,d) -> (a,a,b,b) and (c,c,d,d)
__device__ __forceinline__ void dup_sts(float4* dst, float4 v) {
    dst[0] = make_float4(v.x, v.x, v.y, v.y);
    dst[1] = make_float4(v.z, v.z, v.w, v.w);
}

// ---------------------------------------------------------------------------
// Node transform v5: persistent blocks, dup-X smem, reg-prefetch of next tile.
//   blockIdx.y picks GEMM (W1->Y1 or W2->Y2); W staged ONCE per block.
//   512 threads = 16 warps x 8 rows = 128-row tiles; 4 cols/lane.
//   smem: W 64KB + bias + Xdup 128KB = ~192.5KB (1 block/SM).
// ---------------------------------------------------------------------------
#define NODE_THREADS 512
#define NODE_ROWS    128
#define NODE_RPW     8
#define NODE_SMEM_FLOATS (16384 + 128 + NODE_ROWS * 256)
#define NODE_SMEM_BYTES  (NODE_SMEM_FLOATS * 4)
#define NODE_PF 8   // float4 loads per thread per tile (128*32/512)

__global__ __launch_bounds__(NODE_THREADS, 1)
void node_kernel(const float* __restrict__ X,
                 const float* __restrict__ W1, const float* __restrict__ b1,
                 float* __restrict__ Y1,
                 const float* __restrict__ W2, const float* __restrict__ b2,
                 float* __restrict__ Y2,
                 int n)
{
    extern __shared__ float sm[];
    float* Ws = sm;                  // 128*128
    float* bs = sm + 16384;          // 128
    float* Xd = sm + 16512;          // 128 rows * 256 (duplicated)

    const float* W = blockIdx.y ? W2 : W1;
    const float* b = blockIdx.y ? b2 : b1;
    float*       Y = blockIdx.y ? Y2 : Y1;

    const int tid = threadIdx.x;

    // Stage weights + bias ONCE per persistent block.
    {
        const float4* Wg = (const float4*)W;
        float4* Wsv = (float4*)Ws;
        #pragma unroll
        for (int i = tid; i < 4096; i += NODE_THREADS) Wsv[i] = Wg[i];
        if (tid < 128) bs[tid] = b[tid];
    }

    const int warp = tid >> 5;
    const int lane = tid & 31;
    const int r0 = warp * NODE_RPW;
    const ulonglong2* Wv = (const ulonglong2*)Ws;   // [k*32+lane] = 4 cols
    const ulonglong2* Xv = (const ulonglong2*)Xd;   // [row*64 + 2*k4 (+1)]
    float4* Xdv = (float4*)Xd;
    const float4* Xg = (const float4*)X;

    const int ntiles = (n + NODE_ROWS - 1) / NODE_ROWS;
    const int G = gridDim.x;

    // Load a tile's raw X into regs (NODE_PF float4 per thread).
    float4 pf[NODE_PF];
    int t = blockIdx.x;
    if (t < ntiles) {
        #pragma unroll
        for (int j = 0; j < NODE_PF; j++) {
            int i = tid + j * NODE_THREADS;          // float4 idx in tile
            int row = t * NODE_ROWS + (i >> 5);
            pf[j] = (row < n) ? Xg[(size_t)row * 32 + (i & 31)]
                              : make_float4(0.f, 0.f, 0.f, 0.f);
        }
    }
    __syncthreads();   // Ws ready
    if (t < ntiles) {
        #pragma unroll
        for (int j = 0; j < NODE_PF; j++) {
            int i = tid + j * NODE_THREADS;
            dup_sts(&Xdv[((i >> 5) * 64) + (i & 31) * 2], pf[j]);
        }
    }
    __syncthreads();

    for (; t < ntiles; t += G) {
        const int tn = t + G;

        // Prefetch next tile into regs (overlaps with compute below).
        if (tn < ntiles) {
            #pragma unroll
            for (int j = 0; j < NODE_PF; j++) {
                int i = tid + j * NODE_THREADS;
                int row = tn * NODE_ROWS + (i >> 5);
                pf[j] = (row < n) ? Xg[(size_t)row * 32 + (i & 31)]
                                  : make_float4(0.f, 0.f, 0.f, 0.f);
            }
        }

        F4U2 bias; bias.f = ((const float4*)bs)[lane];
        ulonglong2 acc[NODE_RPW];
        #pragma unroll
        for (int r = 0; r < NODE_RPW; r++) acc[r] = bias.u;

        for (int k4 = 0; k4 < 32; k4++) {
            const int k0 = 4 * k4;
            ulonglong2 w0 = Wv[(k0 + 0) * 32 + lane];
            ulonglong2 w1 = Wv[(k0 + 1) * 32 + lane];
            ulonglong2 w2 = Wv[(k0 + 2) * 32 + lane];
            ulonglong2 w3 = Wv[(k0 + 3) * 32 + lane];
            #pragma unroll
            for (int r = 0; r < NODE_RPW; r++) {
                ulonglong2 p0 = Xv[(r0 + r) * 64 + 2 * k4];     // dup(x0),dup(x1)
                ulonglong2 p1 = Xv[(r0 + r) * 64 + 2 * k4 + 1]; // dup(x2),dup(x3)
                acc[r].x = fma2(p0.x, w0.x, acc[r].x);
                acc[r].y = fma2(p0.x, w0.y, acc[r].y);
                acc[r].x = fma2(p0.y, w1.x, acc[r].x);
                acc[r].y = fma2(p0.y, w1.y, acc[r].y);
                acc[r].x = fma2(p1.x, w2.x, acc[r].x);
                acc[r].y = fma2(p1.x, w2.y, acc[r].y);
                acc[r].x = fma2(p1.y, w3.x, acc[r].x);
                acc[r].y = fma2(p1.y, w3.y, acc[r].y);
            }
        }

        #pragma unroll
        for (int r = 0; r < NODE_RPW; r++) {
            int row = t * NODE_ROWS + r0 + r;
            if (row < n) {
                F4U2 o; o.u = acc[r];
                ((float4*)(Y + (size_t)row * 128))[lane] = o.f;
            }
        }

        __syncthreads();   // all readers done with Xd
        if (tn < ntiles) {
            #pragma unroll
            for (int j = 0; j < NODE_PF; j++) {
                int i = tid + j * NODE_THREADS;
                dup_sts(&Xdv[((i >> 5) * 64) + (i & 31) * 2], pf[j]);
            }
        }
        __syncthreads();
    }
}

// ---------------------------------------------------------------------------
// Relation kernel v6: dup-X smem, 8 edges/warp, reg-prefetch double buffer.
//   * W_edge (32x128, 16KB) staged once per block
//   * 64-edge dup Xe tiles (16KB) + indices, grid-stride
//   * inner loop: zero splat MOVs; acc seeded by XW[src] gather; relu; red.v4
// ---------------------------------------------------------------------------
#define REL_THREADS 256
#define REL_EPW 8
#define REL_TILE 64

__global__ __launch_bounds__(REL_THREADS, 3)
void rel_kernel(const float* __restrict__ XW,
                const float* __restrict__ Xe,
                const int* __restrict__ src,
                const int* __restrict__ dst,
                const float* __restrict__ We,
                float* __restrict__ out,
                int E)
{
    __shared__ float Wes[D_EDGE * D_OUT];        // 16 KB
    __shared__ float Xd[REL_TILE * D_EDGE * 2];  // 16 KB (duplicated)
    __shared__ int   Ss[REL_TILE];
    __shared__ int   Ds[REL_TILE];

    const int tid = threadIdx.x;

    {
        const float4* Weg = (const float4*)We;
        float4* Wesv = (float4*)Wes;
        #pragma unroll
        for (int i = tid; i < (D_EDGE * D_OUT) / 4; i += REL_THREADS)
            Wesv[i] = Weg[i];
    }

    const int warp = tid >> 5;
    const int lane = tid & 31;
    const int r0 = warp * REL_EPW;               // 8 warps * 8 edges = 64
    const ulonglong2* Wv = (const ulonglong2*)Wes;
    const ulonglong2* Xv = (const ulonglong2*)Xd; // [edge*16 + 2*k4 (+1)]
    float4* Xdv = (float4*)Xd;
    const float4* Xeg = (const float4*)Xe;       // E*8 float4 total

    const int ntiles = (E + REL_TILE - 1) / REL_TILE;
    const int G = gridDim.x;
    const int nf4 = E * (D_EDGE / 4);            // total float4 in Xe

    float4 pa, pb;  int pidx = 0;
    int t = blockIdx.x;

    // Prefetch + stage first tile.
    if (t < ntiles) {
        int i0 = t * (REL_TILE * D_EDGE / 4) + tid;
        int i1 = i0 + REL_THREADS;
        pa = (i0 < nf4) ? Xeg[i0] : make_float4(0.f, 0.f, 0.f, 0.f);
        pb = (i1 < nf4) ? Xeg[i1] : make_float4(0.f, 0.f, 0.f, 0.f);
        if (tid < REL_TILE) {
            int e = t * REL_TILE + tid;
            pidx = (e < E) ? __ldg(&src[e]) : 0;
        } else if (tid < 2 * REL_TILE) {
            int e = t * REL_TILE + tid - REL_TILE;
            pidx = (e < E) ? __ldg(&dst[e]) : 0;
        }
    }
    __syncthreads();   // Wes ready
    if (t < ntiles) {
        int i0 = tid, i1 = tid + REL_THREADS;
        dup_sts(&Xdv[((i0 >> 3) * 16) + (i0 & 7) * 2], pa);
        dup_sts(&Xdv[((i1 >> 3) * 16) + (i1 & 7) * 2], pb);
        if (tid < REL_TILE) Ss[tid] = pidx;
        else if (tid < 2 * REL_TILE) Ds[tid - REL_TILE] = pidx;
    }
    __syncthreads();

    for (; t < ntiles; t += G) {
        const int tn = t + G;
        const int e0 = t * REL_TILE;

        // Prefetch next tile into regs.
        if (tn < ntiles) {
            int i0 = tn * (REL_TILE * D_EDGE / 4) + tid;
            int i1 = i0 + REL_THREADS;
            pa = (i0 < nf4) ? Xeg[i0] : make_float4(0.f, 0.f, 0.f, 0.f);
            pb = (i1 < nf4) ? Xeg[i1] : make_float4(0.f, 0.f, 0.f, 0.f);
            if (tid < REL_TILE) {
                int e = tn * REL_TILE + tid;
                pidx = (e < E) ? __ldg(&src[e]) : 0;
            } else if (tid < 2 * REL_TILE) {
                int e = tn * REL_TILE + tid - REL_TILE;
                pidx = (e < E) ? __ldg(&dst[e]) : 0;
            }
        }

        // Seed accumulators with gathered XW rows (bias folded; MLP=8).
        ulonglong2 acc[REL_EPW];
        #pragma unroll
        for (int r = 0; r < REL_EPW; r++) {
            int s = Ss[r0 + r];
            F4U2 g; g.f = __ldg((const float4*)(XW + (size_t)s * 128) + lane);
            acc[r] = g.u;
        }

        #pragma unroll
        for (int k4 = 0; k4 < D_EDGE / 4; k4++) {
            const int k0 = 4 * k4;
            ulonglong2 w0 = Wv[(k0 + 0) * 32 + lane];
            ulonglong2 w1 = Wv[(k0 + 1) * 32 + lane];
            ulonglong2 w2 = Wv[(k0 + 2) * 32 + lane];
            ulonglong2 w3 = Wv[(k0 + 3) * 32 + lane];
            #pragma unroll
            for (int r = 0; r < REL_EPW; r++) {
                ulonglong2 p0 = Xv[(r0 + r) * 16 + 2 * k4];
                ulonglong2 p1 = Xv[(r0 + r) * 16 + 2 * k4 + 1];
                acc[r].x = fma2(p0.x, w0.x, acc[r].x);
                acc[r].y = fma2(p0.x, w0.y, acc[r].y);
                acc[r].x = fma2(p0.y, w1.x, acc[r].x);
                acc[r].y = fma2(p0.y, w1.y, acc[r].y);
                acc[r].x = fma2(p1.x, w2.x, acc[r].x);
                acc[r].y = fma2(p1.x, w2.y, acc[r].y);
                acc[r].x = fma2(p1.y, w3.x, acc[r].x);
                acc[r].y = fma2(p1.y, w3.y, acc[r].y);
            }
        }

        #pragma unroll
        for (int r = 0; r < REL_EPW; r++) {
            if (e0 + r0 + r < E) {
                F4U2 o; o.u = acc[r];
                float4 v = o.f;
                v.x = fmaxf(v.x, 0.f); v.y = fmaxf(v.y, 0.f);
                v.z = fmaxf(v.z, 0.f); v.w = fmaxf(v.w, 0.f);
                red_add_v4(out + (size_t)Ds[r0 + r] * 128 + 4 * lane, v);
            }
        }

        __syncthreads();   // done reading Xd/Ss/Ds
        if (tn < ntiles) {
            int i0 = tid, i1 = tid + REL_THREADS;
            dup_sts(&Xdv[((i0 >> 3) * 16) + (i0 & 7) * 2], pa);
            dup_sts(&Xdv[((i1 >> 3) * 16) + (i1 & 7) * 2], pb);
            if (tid < REL_TILE) Ss[tid] = pidx;
            else if (tid < 2 * REL_TILE) Ds[tid - REL_TILE] = pidx;
        }
        __syncthreads();
    }
}

// ---------------------------------------------------------------------------
// kernel_launch (metadata order unchanged)
// ---------------------------------------------------------------------------
extern "C" void kernel_launch(void* const* d_in, const int* in_sizes, int n_in,
                              void* d_out, int out_size)
{
    const float* X_user   = (const float*)d_in[0];
    const float* X_item   = (const float*)d_in[1];
    const float* Xe_ui    = (const float*)d_in[2];
    const float* Xe_iu    = (const float*)d_in[3];
    const float* W_src_ui = (const float*)d_in[4];
    const float* W_edge_ui= (const float*)d_in[5];
    const float* b_ui     = (const float*)d_in[6];
    const float* W_src_iu = (const float*)d_in[7];
    const float* W_edge_iu= (const float*)d_in[8];
    const float* b_iu     = (const float*)d_in[9];
    const float* Wl_user  = (const float*)d_in[10];
    const float* bl_user  = (const float*)d_in[11];
    const float* Wl_item  = (const float*)d_in[12];
    const float* bl_item  = (const float*)d_in[13];
    const int*   src_ui   = (const int*)d_in[14];
    const int*   dst_ui   = (const int*)d_in[15];
    const int*   src_iu   = (const int*)d_in[16];
    const int*   dst_iu   = (const int*)d_in[17];

    const int n_user = in_sizes[0] / D_IN;
    const int n_item = in_sizes[1] / D_IN;
    const int E      = in_sizes[14];

    float* H_user = (float*)d_out;
    float* H_item = (float*)d_out + (size_t)n_user * D_OUT;

    void* p_xwu = nullptr; void* p_xwi = nullptr;
    cudaGetSymbolAddress(&p_xwu, g_xwu);
    cudaGetSymbolAddress(&p_xwi, g_xwi);
    float* xwu = (float*)p_xwu;
    float* xwi = (float*)p_xwi;

    cudaFuncSetAttribute(node_kernel,
                         cudaFuncAttributeMaxDynamicSharedMemorySize,
                         NODE_SMEM_BYTES);

    // 1 block/SM (192KB smem); (74,2) = one persistent block per SM per GEMM.
    dim3 gnode(74, 2);

    node_kernel<<<gnode, NODE_THREADS, NODE_SMEM_BYTES>>>(
        X_user, W_src_ui, b_ui, xwu, Wl_user, bl_user, H_user, n_user);

    node_kernel<<<gnode, NODE_THREADS, NODE_SMEM_BYTES>>>(
        X_item, W_src_iu, b_iu, xwi, Wl_item, bl_item, H_item, n_item);

    const int rel_grid = 148 * 3;   // 3 blocks/SM
    rel_kernel<<<rel_grid, REL_THREADS>>>(xwu, Xe_ui, src_ui, dst_ui, W_edge_ui, H_item, E);
    rel_kernel<<<rel_grid, REL_THREADS>>>(xwi, Xe_iu, src_iu, dst_iu, W_edge_iu, H_user, E);
}

// round 7
// speedup vs baseline: 1.1508x; 1.1508x over previous
#include <cuda_runtime.h>
#include <cuda_bf16.h>
#include <cstddef>

#define D_IN   128
#define D_OUT  128
#define D_EDGE 32
#define MAX_NODES 100000

__device__ float g_xwu[(size_t)MAX_NODES * D_OUT];
__device__ float g_xwi[(size_t)MAX_NODES * D_OUT];

// ---------------------------------------------------------------------------
// Packed f32x2 helpers (fma.rn.f32x2 only reachable via PTX on sm_10x).
// ---------------------------------------------------------------------------
__device__ __forceinline__ unsigned long long pk2(float x) {
    unsigned long long r;
    asm("mov.b64 %0, {%1, %1};" : "=l"(r) : "f"(x));
    return r;
}
__device__ __forceinline__ unsigned long long fma2(unsigned long long a,
                                                   unsigned long long b,
                                                   unsigned long long c) {
    unsigned long long d;
    asm("fma.rn.f32x2 %0, %1, %2, %3;" : "=l"(d) : "l"(a), "l"(b), "l"(c));
    return d;
}

union F4U2 { float4 f; ulonglong2 u; };

__device__ __forceinline__ void red_add_v4(float* p, float4 v) {
    asm volatile("red.global.add.v4.f32 [%0], {%1,%2,%3,%4};"
                 :: "l"(p), "f"(v.x), "f"(v.y), "f"(v.z), "f"(v.w)
                 : "memory");
}

// ---------------------------------------------------------------------------
// Node transform v7: 256 threads, 8 rows/warp, 64-row tiles, 2 blocks/SM.
//   blockIdx.y picks GEMM (W1->Y1 or W2->Y2); W staged once per block;
//   persistent grid-stride over tiles with register prefetch of next X tile.
// ---------------------------------------------------------------------------
#define NODE_THREADS 256
#define NODE_ROWS    64
#define NODE_RPW     8
#define NODE_PF      8   // float4 per thread per tile: 64*32/256
#define NODE_SMEM_FLOATS (16384 + 128 + NODE_ROWS * 128)
#define NODE_SMEM_BYTES  (NODE_SMEM_FLOATS * 4)

__global__ __launch_bounds__(NODE_THREADS, 2)
void node_kernel(const float* __restrict__ X,
                 const float* __restrict__ W1, const float* __restrict__ b1,
                 float* __restrict__ Y1,
                 const float* __restrict__ W2, const float* __restrict__ b2,
                 float* __restrict__ Y2,
                 int n)
{
    extern __shared__ float sm[];
    float* Ws = sm;                  // 128*128
    float* bs = sm + 16384;          // 128
    float* Xs = sm + 16512;          // 64 * 128

    const float* W = blockIdx.y ? W2 : W1;
    const float* b = blockIdx.y ? b2 : b1;
    float*       Y = blockIdx.y ? Y2 : Y1;

    const int tid = threadIdx.x;

    {   // Stage W + bias once per persistent block.
        const float4* Wg = (const float4*)W;
        float4* Wsv = (float4*)Ws;
        #pragma unroll
        for (int i = tid; i < 4096; i += NODE_THREADS) Wsv[i] = Wg[i];
        if (tid < 128) bs[tid] = b[tid];
    }

    const int warp = tid >> 5;
    const int lane = tid & 31;
    const int r0 = warp * NODE_RPW;
    const ulonglong2* Wv = (const ulonglong2*)Ws;
    float4* Xsv = (float4*)Xs;
    const float4* Xg = (const float4*)X;

    const int ntiles = (n + NODE_ROWS - 1) / NODE_ROWS;
    const int G = gridDim.x;

    float4 pf[NODE_PF];
    int t = blockIdx.x;
    if (t < ntiles) {
        #pragma unroll
        for (int j = 0; j < NODE_PF; j++) {
            int i = tid + j * NODE_THREADS;
            int row = t * NODE_ROWS + (i >> 5);
            pf[j] = (row < n) ? Xg[(size_t)row * 32 + (i & 31)]
                              : make_float4(0.f, 0.f, 0.f, 0.f);
        }
    }
    __syncthreads();          // Ws staged
    if (t < ntiles) {
        #pragma unroll
        for (int j = 0; j < NODE_PF; j++) {
            int i = tid + j * NODE_THREADS;
            Xsv[i] = pf[j];
        }
    }
    __syncthreads();

    for (; t < ntiles; t += G) {
        const int tn = t + G;

        if (tn < ntiles) {    // prefetch next X tile (hidden under compute)
            #pragma unroll
            for (int j = 0; j < NODE_PF; j++) {
                int i = tid + j * NODE_THREADS;
                int row = tn * NODE_ROWS + (i >> 5);
                pf[j] = (row < n) ? Xg[(size_t)row * 32 + (i & 31)]
                                  : make_float4(0.f, 0.f, 0.f, 0.f);
            }
        }

        F4U2 bias; bias.f = ((const float4*)bs)[lane];
        ulonglong2 acc[NODE_RPW];
        #pragma unroll
        for (int r = 0; r < NODE_RPW; r++) acc[r] = bias.u;

        #pragma unroll 4
        for (int k4 = 0; k4 < 32; k4++) {
            const int k0 = 4 * k4;
            ulonglong2 w0 = Wv[(k0 + 0) * 32 + lane];
            ulonglong2 w1 = Wv[(k0 + 1) * 32 + lane];
            ulonglong2 w2 = Wv[(k0 + 2) * 32 + lane];
            ulonglong2 w3 = Wv[(k0 + 3) * 32 + lane];
            #pragma unroll
            for (int r = 0; r < NODE_RPW; r++) {
                float4 xv = *(const float4*)&Xs[(r0 + r) * 128 + k0];
                unsigned long long xa = pk2(xv.x);
                unsigned long long xb = pk2(xv.y);
                unsigned long long xc = pk2(xv.z);
                unsigned long long xd = pk2(xv.w);
                acc[r].x = fma2(xa, w0.x, acc[r].x);
                acc[r].y = fma2(xa, w0.y, acc[r].y);
                acc[r].x = fma2(xb, w1.x, acc[r].x);
                acc[r].y = fma2(xb, w1.y, acc[r].y);
                acc[r].x = fma2(xc, w2.x, acc[r].x);
                acc[r].y = fma2(xc, w2.y, acc[r].y);
                acc[r].x = fma2(xd, w3.x, acc[r].x);
                acc[r].y = fma2(xd, w3.y, acc[r].y);
            }
        }

        #pragma unroll
        for (int r = 0; r < NODE_RPW; r++) {
            int row = t * NODE_ROWS + r0 + r;
            if (row < n) {
                F4U2 o; o.u = acc[r];
                ((float4*)(Y + (size_t)row * 128))[lane] = o.f;
            }
        }

        __syncthreads();
        if (tn < ntiles) {
            #pragma unroll
            for (int j = 0; j < NODE_PF; j++) {
                int i = tid + j * NODE_THREADS;
                Xsv[i] = pf[j];
            }
        }
        __syncthreads();
    }
}

// ---------------------------------------------------------------------------
// Relation kernel v7: latency-pipelined.
//   * indices live in lanes (lane<8: src, lane 8..15: dst), shfl broadcast;
//     loaded TWO tiles ahead.
//   * XW[src] gathers issued ONE tile ahead into registers (gn), consumed
//     the next iteration -> ~600cyc of cover for the L2 gather latency.
//   * Xe tile (64 edges, 8KB) reg-prefetched, restaged after sync.
//   * W_edge 16KB smem staged once; f32x2 FMA inner loop.
// ---------------------------------------------------------------------------
#define REL_THREADS 256
#define REL_EPW 8
#define REL_TILE 64

__device__ __forceinline__ int rel_load_idx(const int* __restrict__ src,
                                            const int* __restrict__ dst,
                                            int ebase, int lane, int E) {
    if (lane < 8) {
        int e = ebase + lane;
        return (e < E) ? __ldg(src + e) : 0;
    } else if (lane < 16) {
        int e = ebase + lane - 8;
        return (e < E) ? __ldg(dst + e) : 0;
    }
    return 0;
}

__global__ __launch_bounds__(REL_THREADS, 2)
void rel_kernel(const float* __restrict__ XW,
                const float* __restrict__ Xe,
                const int* __restrict__ src,
                const int* __restrict__ dst,
                const float* __restrict__ We,
                float* __restrict__ out,
                int E)
{
    __shared__ float Wes[D_EDGE * D_OUT];    // 16 KB
    __shared__ float Xs[REL_TILE * D_EDGE];  // 8 KB

    const int tid = threadIdx.x;
    {
        const float4* Weg = (const float4*)We;
        float4* Wesv = (float4*)Wes;
        #pragma unroll
        for (int i = tid; i < (D_EDGE * D_OUT) / 4; i += REL_THREADS)
            Wesv[i] = Weg[i];
    }

    const int warp = tid >> 5;
    const int lane = tid & 31;
    const int r0 = warp * REL_EPW;           // 8 warps * 8 edges = 64
    const ulonglong2* Wv = (const ulonglong2*)Wes;
    float4* Xsv = (float4*)Xs;
    const float4* Xeg = (const float4*)Xe;

    const int ntiles = (E + REL_TILE - 1) / REL_TILE;
    const int G = gridDim.x;
    const int nf4 = E * (D_EDGE / 4);

    int t = blockIdx.x;

    // --- pre-pipeline: indices for t and t+G, gathers for t, Xe tile t ---
    int idx_cur  = rel_load_idx(src, dst, t * REL_TILE + warp * 8, lane, E);
    int idx_next = rel_load_idx(src, dst, (t + G) * REL_TILE + warp * 8, lane, E);

    F4U2 gc[REL_EPW];
    #pragma unroll
    for (int r = 0; r < REL_EPW; r++) {
        int s = __shfl_sync(0xffffffffu, idx_cur, r);
        gc[r].f = __ldg((const float4*)(XW + (size_t)s * 128) + lane);
    }

    float4 pa = make_float4(0.f, 0.f, 0.f, 0.f);
    float4 pb = pa;
    if (t < ntiles) {
        int i0 = t * (REL_TILE * D_EDGE / 4) + tid;
        int i1 = i0 + REL_THREADS;
        if (i0 < nf4) pa = Xeg[i0];
        if (i1 < nf4) pb = Xeg[i1];
    }
    __syncthreads();          // Wes staged
    if (t < ntiles) { Xsv[tid] = pa; Xsv[tid + REL_THREADS] = pb; }
    __syncthreads();

    for (; t < ntiles; t += G) {
        const int tn = t + G;
        const int e0 = t * REL_TILE;

        // Gather for NEXT tile (idx_next already resident).
        F4U2 gn[REL_EPW];
        #pragma unroll
        for (int r = 0; r < REL_EPW; r++) {
            int s = __shfl_sync(0xffffffffu, idx_next, r);
            gn[r].f = __ldg((const float4*)(XW + (size_t)s * 128) + lane);
        }
        // Indices two tiles ahead.
        int idx_n2 = rel_load_idx(src, dst, (t + 2 * G) * REL_TILE + warp * 8, lane, E);
        // Prefetch Xe for next tile.
        if (tn < ntiles) {
            int i0 = tn * (REL_TILE * D_EDGE / 4) + tid;
            int i1 = i0 + REL_THREADS;
            pa = (i0 < nf4) ? Xeg[i0] : make_float4(0.f, 0.f, 0.f, 0.f);
            pb = (i1 < nf4) ? Xeg[i1] : make_float4(0.f, 0.f, 0.f, 0.f);
        }

        // Compute tile t: acc seeded from gathered XW rows (bias folded).
        ulonglong2 acc[REL_EPW];
        #pragma unroll
        for (int r = 0; r < REL_EPW; r++) acc[r] = gc[r].u;

        #pragma unroll
        for (int k4 = 0; k4 < D_EDGE / 4; k4++) {
            const int k0 = 4 * k4;
            ulonglong2 w0 = Wv[(k0 + 0) * 32 + lane];
            ulonglong2 w1 = Wv[(k0 + 1) * 32 + lane];
            ulonglong2 w2 = Wv[(k0 + 2) * 32 + lane];
            ulonglong2 w3 = Wv[(k0 + 3) * 32 + lane];
            #pragma unroll
            for (int r = 0; r < REL_EPW; r++) {
                float4 xv = *(const float4*)&Xs[(r0 + r) * D_EDGE + k0];
                unsigned long long xa = pk2(xv.x);
                unsigned long long xb = pk2(xv.y);
                unsigned long long xc = pk2(xv.z);
                unsigned long long xd = pk2(xv.w);
                acc[r].x = fma2(xa, w0.x, acc[r].x);
                acc[r].y = fma2(xa, w0.y, acc[r].y);
                acc[r].x = fma2(xb, w1.x, acc[r].x);
                acc[r].y = fma2(xb, w1.y, acc[r].y);
                acc[r].x = fma2(xc, w2.x, acc[r].x);
                acc[r].y = fma2(xc, w2.y, acc[r].y);
                acc[r].x = fma2(xd, w3.x, acc[r].x);
                acc[r].y = fma2(xd, w3.y, acc[r].y);
            }
        }

        #pragma unroll
        for (int r = 0; r < REL_EPW; r++) {
            if (e0 + r0 + r < E) {
                int d = __shfl_sync(0xffffffffu, idx_cur, r + 8);
                F4U2 o; o.u = acc[r];
                float4 v = o.f;
                v.x = fmaxf(v.x, 0.f); v.y = fmaxf(v.y, 0.f);
                v.z = fmaxf(v.z, 0.f); v.w = fmaxf(v.w, 0.f);
                red_add_v4(out + (size_t)d * 128 + 4 * lane, v);
            }
        }

        __syncthreads();
        if (tn < ntiles) { Xsv[tid] = pa; Xsv[tid + REL_THREADS] = pb; }
        __syncthreads();

        // rotate pipeline state
        #pragma unroll
        for (int r = 0; r < REL_EPW; r++) gc[r] = gn[r];
        idx_cur = idx_next;
        idx_next = idx_n2;
    }
}

// ---------------------------------------------------------------------------
// kernel_launch (metadata order unchanged)
// ---------------------------------------------------------------------------
extern "C" void kernel_launch(void* const* d_in, const int* in_sizes, int n_in,
                              void* d_out, int out_size)
{
    const float* X_user   = (const float*)d_in[0];
    const float* X_item   = (const float*)d_in[1];
    const float* Xe_ui    = (const float*)d_in[2];
    const float* Xe_iu    = (const float*)d_in[3];
    const float* W_src_ui = (const float*)d_in[4];
    const float* W_edge_ui= (const float*)d_in[5];
    const float* b_ui     = (const float*)d_in[6];
    const float* W_src_iu = (const float*)d_in[7];
    const float* W_edge_iu= (const float*)d_in[8];
    const float* b_iu     = (const float*)d_in[9];
    const float* Wl_user  = (const float*)d_in[10];
    const float* bl_user  = (const float*)d_in[11];
    const float* Wl_item  = (const float*)d_in[12];
    const float* bl_item  = (const float*)d_in[13];
    const int*   src_ui   = (const int*)d_in[14];
    const int*   dst_ui   = (const int*)d_in[15];
    const int*   src_iu   = (const int*)d_in[16];
    const int*   dst_iu   = (const int*)d_in[17];

    const int n_user = in_sizes[0] / D_IN;
    const int n_item = in_sizes[1] / D_IN;
    const int E      = in_sizes[14];

    float* H_user = (float*)d_out;
    float* H_item = (float*)d_out + (size_t)n_user * D_OUT;

    void* p_xwu = nullptr; void* p_xwi = nullptr;
    cudaGetSymbolAddress(&p_xwu, g_xwu);
    cudaGetSymbolAddress(&p_xwi, g_xwi);
    float* xwu = (float*)p_xwu;
    float* xwi = (float*)p_xwi;

    cudaFuncSetAttribute(node_kernel,
                         cudaFuncAttributeMaxDynamicSharedMemorySize,
                         NODE_SMEM_BYTES);

    // 2 blocks/SM: x=148 persistent blocks per GEMM, y picks the GEMM.
    dim3 gnode(148, 2);

    node_kernel<<<gnode, NODE_THREADS, NODE_SMEM_BYTES>>>(
        X_user, W_src_ui, b_ui, xwu, Wl_user, bl_user, H_user, n_user);

    node_kernel<<<gnode, NODE_THREADS, NODE_SMEM_BYTES>>>(
        X_item, W_src_iu, b_iu, xwi, Wl_item, bl_item, H_item, n_item);

    const int rel_grid = 148 * 2;   // 2 blocks/SM
    rel_kernel<<<rel_grid, REL_THREADS>>>(xwu, Xe_ui, src_ui, dst_ui, W_edge_ui, H_item, E);
    rel_kernel<<<rel_grid, REL_THREADS>>>(xwi, Xe_iu, src_iu, dst_iu, W_edge_iu, H_user, E);
}

// round 9
// speedup vs baseline: 1.2365x; 1.0745x over previous
#include <cuda_runtime.h>
#include <cuda_bf16.h>
#include <cstdint>
#include <cstddef>

#define D_IN   128
#define D_OUT  128
#define D_EDGE 32
#define MAX_NODES 100000

__device__ float g_xwu[(size_t)MAX_NODES * D_OUT];
__device__ float g_xwi[(size_t)MAX_NODES * D_OUT];

// ============================= common helpers ==============================
__device__ __forceinline__ unsigned long long pk2(float x) {
    unsigned long long r;
    asm("mov.b64 %0, {%1, %1};" : "=l"(r) : "f"(x));
    return r;
}
__device__ __forceinline__ unsigned long long fma2(unsigned long long a,
                                                   unsigned long long b,
                                                   unsigned long long c) {
    unsigned long long d;
    asm("fma.rn.f32x2 %0, %1, %2, %3;" : "=l"(d) : "l"(a), "l"(b), "l"(c));
    return d;
}
union F4U2 { float4 f; ulonglong2 u; };

__device__ __forceinline__ void red_add_v4(float* p, float4 v) {
    asm volatile("red.global.add.v4.f32 [%0], {%1,%2,%3,%4};"
                 :: "l"(p), "f"(v.x), "f"(v.y), "f"(v.z), "f"(v.w)
                 : "memory");
}
__device__ __forceinline__ uint32_t smem_u32(const void* p) {
    uint32_t a;
    asm("{ .reg .u64 t; cvta.to.shared.u64 t, %1; cvt.u32.u64 %0, t; }"
        : "=r"(a) : "l"(p));
    return a;
}
__device__ __forceinline__ uint32_t bf2bits(__nv_bfloat162 h) {
    return *reinterpret_cast<uint32_t*>(&h);
}
// fp32 -> bf16 hi/lo split of a float4 (4 consecutive columns).
__device__ __forceinline__ void cvt_hi_lo(float4 x, uint2& hi, uint2& lo) {
    __nv_bfloat162 h01 = __floats2bfloat162_rn(x.x, x.y);
    __nv_bfloat162 h23 = __floats2bfloat162_rn(x.z, x.w);
    float2 f01 = __bfloat1622float2(h01);
    float2 f23 = __bfloat1622float2(h23);
    __nv_bfloat162 l01 = __floats2bfloat162_rn(x.x - f01.x, x.y - f01.y);
    __nv_bfloat162 l23 = __floats2bfloat162_rn(x.z - f23.x, x.w - f23.y);
    hi = make_uint2(bf2bits(h01), bf2bits(h23));
    lo = make_uint2(bf2bits(l01), bf2bits(l23));
}

#define LDSM4(r, addr) \
    asm volatile("ldmatrix.sync.aligned.m8n8.x4.shared.b16 {%0,%1,%2,%3}, [%4];" \
        : "=r"((r)[0]), "=r"((r)[1]), "=r"((r)[2]), "=r"((r)[3]) : "r"(addr))
#define LDSM4T(r, addr) \
    asm volatile("ldmatrix.sync.aligned.m8n8.x4.trans.shared.b16 {%0,%1,%2,%3}, [%4];" \
        : "=r"((r)[0]), "=r"((r)[1]), "=r"((r)[2]), "=r"((r)[3]) : "r"(addr))
#define MMA16816(c, a, b0_, b1_) \
    asm volatile("mma.sync.aligned.m16n8k16.row.col.f32.bf16.bf16.f32 " \
        "{%0,%1,%2,%3}, {%4,%5,%6,%7}, {%8,%9}, {%0,%1,%2,%3};" \
        : "+f"((c)[0]), "+f"((c)[1]), "+f"((c)[2]), "+f"((c)[3]) \
        : "r"((a)[0]), "r"((a)[1]), "r"((a)[2]), "r"((a)[3]), "r"(b0_), "r"(b1_))

// ---------------------------------------------------------------------------
// Node stage, tensor-core version (mma.sync bf16x3, baseline PTX sm_80+).
// ONE persistent kernel covers all 4 GEMMs:
//   seg0: xwu    = X_user @ W_src_ui + b_ui
//   seg1: H_user = X_user @ Wl_user  + bl_user
//   seg2: xwi    = X_item @ W_src_iu + b_iu
//   seg3: H_item = X_item @ Wl_item  + bl_item
// Tile = 128 rows x 128 cols, K=128. 512 threads = 16 warps; warp w computes
// rows (w/2)*16..+15, cols (w&1)*64..+63 as 8 m16n8 fp32 fragments.
// smem: X hi/lo + W hi/lo, 272B row stride (conflict-free ldmatrix).
// ---------------------------------------------------------------------------
#define NT_THREADS 512
#define XSTRIDE    272
#define NXHI 0
#define NXLO 34816
#define NWHI 69632
#define NWLO 104448
#define NBS  139264
#define NT_SMEM (139264 + 512)

__global__ __launch_bounds__(NT_THREADS, 1)
void node_tc_kernel(const float* __restrict__ Xu, const float* __restrict__ Xi,
                    const float* __restrict__ Wsu, const float* __restrict__ bu,
                    float* __restrict__ xwu,
                    const float* __restrict__ Wlu, const float* __restrict__ blu,
                    float* __restrict__ Hu,
                    const float* __restrict__ Wsi, const float* __restrict__ bi,
                    float* __restrict__ xwi,
                    const float* __restrict__ Wli, const float* __restrict__ bli,
                    float* __restrict__ Hi,
                    int nu, int ni)
{
    extern __shared__ char smem[];
    const uint32_t sbase = smem_u32(smem);
    float* bs = (float*)(smem + NBS);

    const int tid  = threadIdx.x;
    const int warp = tid >> 5;
    const int lane = tid & 31;
    const int r0 = (warp >> 1) * 16;          // warp row base within tile
    const int n0 = (warp & 1) * 64;           // warp col base

    const float* Xs_[4] = {Xu, Xu, Xi, Xi};
    const float* Ws_[4] = {Wsu, Wlu, Wsi, Wli};
    const float* bs_[4] = {bu, blu, bi, bli};
    float*       Ys_[4] = {xwu, Hu, xwi, Hi};
    const int    ns_[4] = {nu, nu, ni, ni};

    const int tu = (nu + 127) >> 7;
    const int ti = (ni + 127) >> 7;
    const int cum[5] = {0, tu, 2 * tu, 2 * tu + ti, 2 * tu + 2 * ti};
    const int total = cum[4];

    // ldmatrix lane address components.
    // A (row-major m16k16): lanes 0-15 rows, 16-31 rows at k+8.
    const uint32_t a_off = (uint32_t)((r0 + (lane & 15)) * XSTRIDE + (lane >> 4) * 16);
    // B (.trans, W row-major k x n): groups of 8 lanes:
    //   g0: k+(l&7), n0 ; g1: k+8+(l&7), n0 ; g2: k+(l&7), n0+8 ; g3: k+8+.., n0+8
    const int bg = lane >> 3;
    const uint32_t b_off = (uint32_t)(((lane & 7) + (bg & 1) * 8) * XSTRIDE
                                      + (n0 + (bg >> 1) * 8) * 2);

    int cur_seg = -1;

    for (int t = blockIdx.x; t < total; t += gridDim.x) {
        int seg = (t >= cum[2]) ? ((t >= cum[3]) ? 3 : 2)
                                : ((t >= cum[1]) ? 1 : 0);
        const int lt = t - cum[seg];
        const int n = ns_[seg];
        const int row_base = lt * 128;
        const float4* Xg = (const float4*)Xs_[seg];
        float* Y = Ys_[seg];

        if (seg != cur_seg) {
            __syncthreads();   // old W readers done
            const float4* Wg = (const float4*)Ws_[seg];
            #pragma unroll
            for (int j = 0; j < 8; j++) {
                int idx = tid + j * NT_THREADS;      // float4 index, 4096 total
                int row = idx >> 5, c4 = idx & 31;
                uint2 hi, lo;
                cvt_hi_lo(Wg[row * 32 + c4], hi, lo);
                *(uint2*)(smem + NWHI + row * XSTRIDE + c4 * 8) = hi;
                *(uint2*)(smem + NWLO + row * XSTRIDE + c4 * 8) = lo;
            }
            if (tid < 128) bs[tid] = bs_[seg][tid];
            cur_seg = seg;
        }

        __syncthreads();       // previous tile's X readers done
        #pragma unroll
        for (int j = 0; j < 8; j++) {
            int idx = tid + j * NT_THREADS;
            int row = idx >> 5, c4 = idx & 31;
            int grow = row_base + row;
            float4 x = (grow < n) ? Xg[(size_t)grow * 32 + c4]
                                  : make_float4(0.f, 0.f, 0.f, 0.f);
            uint2 hi, lo;
            cvt_hi_lo(x, hi, lo);
            *(uint2*)(smem + NXHI + row * XSTRIDE + c4 * 8) = hi;
            *(uint2*)(smem + NXLO + row * XSTRIDE + c4 * 8) = lo;
        }
        __syncthreads();

        float acc[8][4];
        #pragma unroll
        for (int i = 0; i < 8; i++)
            #pragma unroll
            for (int j = 0; j < 4; j++) acc[i][j] = 0.f;

        #pragma unroll
        for (int k0 = 0; k0 < 128; k0 += 16) {
            uint32_t ah[4], al[4];
            uint32_t aaddr = sbase + NXHI + a_off + k0 * 2;
            LDSM4(ah, aaddr);
            LDSM4(al, aaddr + (NXLO - NXHI));
            #pragma unroll
            for (int c = 0; c < 4; c++) {
                uint32_t bh[4], bl[4];
                uint32_t baddr = sbase + NWHI + b_off + k0 * XSTRIDE + c * 32;
                LDSM4T(bh, baddr);
                LDSM4T(bl, baddr + (NWLO - NWHI));
                MMA16816(acc[2 * c],     ah, bh[0], bh[1]);
                MMA16816(acc[2 * c + 1], ah, bh[2], bh[3]);
                MMA16816(acc[2 * c],     ah, bl[0], bl[1]);
                MMA16816(acc[2 * c + 1], ah, bl[2], bl[3]);
                MMA16816(acc[2 * c],     al, bh[0], bh[1]);
                MMA16816(acc[2 * c + 1], al, bh[2], bh[3]);
            }
        }

        // Store + bias. Fragment: c0,c1 -> row lane/4, cols 2(lane&3)(+1);
        // c2,c3 -> row lane/4+8.
        const int ra = row_base + r0 + (lane >> 2);
        const int rb = ra + 8;
        #pragma unroll
        for (int c8 = 0; c8 < 8; c8++) {
            int col = n0 + c8 * 8 + 2 * (lane & 3);
            float b0 = bs[col], b1 = bs[col + 1];
            if (ra < n) {
                float2 v = make_float2(acc[c8][0] + b0, acc[c8][1] + b1);
                *(float2*)(Y + (size_t)ra * 128 + col) = v;
            }
            if (rb < n) {
                float2 v = make_float2(acc[c8][2] + b0, acc[c8][3] + b1);
                *(float2*)(Y + (size_t)rb * 128 + col) = v;
            }
        }
    }
}

// ---------------------------------------------------------------------------
// Relation kernel (R7, unchanged): latency-pipelined FFMA2.
// ---------------------------------------------------------------------------
#define REL_THREADS 256
#define REL_EPW 8
#define REL_TILE 64

__device__ __forceinline__ int rel_load_idx(const int* __restrict__ src,
                                            const int* __restrict__ dst,
                                            int ebase, int lane, int E) {
    if (lane < 8) {
        int e = ebase + lane;
        return (e < E) ? __ldg(src + e) : 0;
    } else if (lane < 16) {
        int e = ebase + lane - 8;
        return (e < E) ? __ldg(dst + e) : 0;
    }
    return 0;
}

__global__ __launch_bounds__(REL_THREADS, 2)
void rel_kernel(const float* __restrict__ XW,
                const float* __restrict__ Xe,
                const int* __restrict__ src,
                const int* __restrict__ dst,
                const float* __restrict__ We,
                float* __restrict__ out,
                int E)
{
    __shared__ float Wes[D_EDGE * D_OUT];
    __shared__ float Xs[REL_TILE * D_EDGE];

    const int tid = threadIdx.x;
    {
        const float4* Weg = (const float4*)We;
        float4* Wesv = (float4*)Wes;
        #pragma unroll
        for (int i = tid; i < (D_EDGE * D_OUT) / 4; i += REL_THREADS)
            Wesv[i] = Weg[i];
    }

    const int warp = tid >> 5;
    const int lane = tid & 31;
    const int r0 = warp * REL_EPW;
    const ulonglong2* Wv = (const ulonglong2*)Wes;
    float4* Xsv = (float4*)Xs;
    const float4* Xeg = (const float4*)Xe;

    const int ntiles = (E + REL_TILE - 1) / REL_TILE;
    const int G = gridDim.x;
    const int nf4 = E * (D_EDGE / 4);

    int t = blockIdx.x;

    int idx_cur  = rel_load_idx(src, dst, t * REL_TILE + warp * 8, lane, E);
    int idx_next = rel_load_idx(src, dst, (t + G) * REL_TILE + warp * 8, lane, E);

    F4U2 gc[REL_EPW];
    #pragma unroll
    for (int r = 0; r < REL_EPW; r++) {
        int s = __shfl_sync(0xffffffffu, idx_cur, r);
        gc[r].f = __ldg((const float4*)(XW + (size_t)s * 128) + lane);
    }

    float4 pa = make_float4(0.f, 0.f, 0.f, 0.f);
    float4 pb = pa;
    if (t < ntiles) {
        int i0 = t * (REL_TILE * D_EDGE / 4) + tid;
        int i1 = i0 + REL_THREADS;
        if (i0 < nf4) pa = Xeg[i0];
        if (i1 < nf4) pb = Xeg[i1];
    }
    __syncthreads();
    if (t < ntiles) { Xsv[tid] = pa; Xsv[tid + REL_THREADS] = pb; }
    __syncthreads();

    for (; t < ntiles; t += G) {
        const int tn = t + G;
        const int e0 = t * REL_TILE;

        F4U2 gn[REL_EPW];
        #pragma unroll
        for (int r = 0; r < REL_EPW; r++) {
            int s = __shfl_sync(0xffffffffu, idx_next, r);
            gn[r].f = __ldg((const float4*)(XW + (size_t)s * 128) + lane);
        }
        int idx_n2 = rel_load_idx(src, dst, (t + 2 * G) * REL_TILE + warp * 8, lane, E);
        if (tn < ntiles) {
            int i0 = tn * (REL_TILE * D_EDGE / 4) + tid;
            int i1 = i0 + REL_THREADS;
            pa = (i0 < nf4) ? Xeg[i0] : make_float4(0.f, 0.f, 0.f, 0.f);
            pb = (i1 < nf4) ? Xeg[i1] : make_float4(0.f, 0.f, 0.f, 0.f);
        }

        ulonglong2 acc[REL_EPW];
        #pragma unroll
        for (int r = 0; r < REL_EPW; r++) acc[r] = gc[r].u;

        #pragma unroll
        for (int k4 = 0; k4 < D_EDGE / 4; k4++) {
            const int k0 = 4 * k4;
            ulonglong2 w0 = Wv[(k0 + 0) * 32 + lane];
            ulonglong2 w1 = Wv[(k0 + 1) * 32 + lane];
            ulonglong2 w2 = Wv[(k0 + 2) * 32 + lane];
            ulonglong2 w3 = Wv[(k0 + 3) * 32 + lane];
            #pragma unroll
            for (int r = 0; r < REL_EPW; r++) {
                float4 xv = *(const float4*)&Xs[(r0 + r) * D_EDGE + k0];
                unsigned long long xa = pk2(xv.x);
                unsigned long long xb = pk2(xv.y);
                unsigned long long xc = pk2(xv.z);
                unsigned long long xd = pk2(xv.w);
                acc[r].x = fma2(xa, w0.x, acc[r].x);
                acc[r].y = fma2(xa, w0.y, acc[r].y);
                acc[r].x = fma2(xb, w1.x, acc[r].x);
                acc[r].y = fma2(xb, w1.y, acc[r].y);
                acc[r].x = fma2(xc, w2.x, acc[r].x);
                acc[r].y = fma2(xc, w2.y, acc[r].y);
                acc[r].x = fma2(xd, w3.x, acc[r].x);
                acc[r].y = fma2(xd, w3.y, acc[r].y);
            }
        }

        #pragma unroll
        for (int r = 0; r < REL_EPW; r++) {
            if (e0 + r0 + r < E) {
                int d = __shfl_sync(0xffffffffu, idx_cur, r + 8);
                F4U2 o; o.u = acc[r];
                float4 v = o.f;
                v.x = fmaxf(v.x, 0.f); v.y = fmaxf(v.y, 0.f);
                v.z = fmaxf(v.z, 0.f); v.w = fmaxf(v.w, 0.f);
                red_add_v4(out + (size_t)d * 128 + 4 * lane, v);
            }
        }

        __syncthreads();
        if (tn < ntiles) { Xsv[tid] = pa; Xsv[tid + REL_THREADS] = pb; }
        __syncthreads();

        #pragma unroll
        for (int r = 0; r < REL_EPW; r++) gc[r] = gn[r];
        idx_cur = idx_next;
        idx_next = idx_n2;
    }
}

// ---------------------------------------------------------------------------
// kernel_launch (metadata order unchanged)
// ---------------------------------------------------------------------------
extern "C" void kernel_launch(void* const* d_in, const int* in_sizes, int n_in,
                              void* d_out, int out_size)
{
    const float* X_user   = (const float*)d_in[0];
    const float* X_item   = (const float*)d_in[1];
    const float* Xe_ui    = (const float*)d_in[2];
    const float* Xe_iu    = (const float*)d_in[3];
    const float* W_src_ui = (const float*)d_in[4];
    const float* W_edge_ui= (const float*)d_in[5];
    const float* b_ui     = (const float*)d_in[6];
    const float* W_src_iu = (const float*)d_in[7];
    const float* W_edge_iu= (const float*)d_in[8];
    const float* b_iu     = (const float*)d_in[9];
    const float* Wl_user  = (const float*)d_in[10];
    const float* bl_user  = (const float*)d_in[11];
    const float* Wl_item  = (const float*)d_in[12];
    const float* bl_item  = (const float*)d_in[13];
    const int*   src_ui   = (const int*)d_in[14];
    const int*   dst_ui   = (const int*)d_in[15];
    const int*   src_iu   = (const int*)d_in[16];
    const int*   dst_iu   = (const int*)d_in[17];

    const int n_user = in_sizes[0] / D_IN;
    const int n_item = in_sizes[1] / D_IN;
    const int E      = in_sizes[14];

    float* H_user = (float*)d_out;
    float* H_item = (float*)d_out + (size_t)n_user * D_OUT;

    void* p_xwu = nullptr; void* p_xwi = nullptr;
    cudaGetSymbolAddress(&p_xwu, g_xwu);
    cudaGetSymbolAddress(&p_xwi, g_xwi);
    float* xwu = (float*)p_xwu;
    float* xwi = (float*)p_xwi;

    cudaFuncSetAttribute(node_tc_kernel,
                         cudaFuncAttributeMaxDynamicSharedMemorySize,
                         NT_SMEM);

    node_tc_kernel<<<148, NT_THREADS, NT_SMEM>>>(
        X_user, X_item,
        W_src_ui, b_ui, xwu,
        Wl_user, bl_user, H_user,
        W_src_iu, b_iu, xwi,
        Wl_item, bl_item, H_item,
        n_user, n_item);

    const int rel_grid = 148 * 2;
    rel_kernel<<<rel_grid, REL_THREADS>>>(xwu, Xe_ui, src_ui, dst_ui, W_edge_ui, H_item, E);
    rel_kernel<<<rel_grid, REL_THREADS>>>(xwi, Xe_iu, src_iu, dst_iu, W_edge_iu, H_user, E);
}

// round 10
// speedup vs baseline: 1.4786x; 1.1957x over previous
#include <cuda_runtime.h>
#include <cuda_bf16.h>
#include <cstdint>
#include <cstddef>

#define D_IN   128
#define D_OUT  128
#define D_EDGE 32
#define MAX_NODES 100000

__device__ float g_xwu[(size_t)MAX_NODES * D_OUT];
__device__ float g_xwi[(size_t)MAX_NODES * D_OUT];

// ============================= common helpers ==============================
__device__ __forceinline__ unsigned long long pk2(float x) {
    unsigned long long r;
    asm("mov.b64 %0, {%1, %1};" : "=l"(r) : "f"(x));
    return r;
}
__device__ __forceinline__ unsigned long long fma2(unsigned long long a,
                                                   unsigned long long b,
                                                   unsigned long long c) {
    unsigned long long d;
    asm("fma.rn.f32x2 %0, %1, %2, %3;" : "=l"(d) : "l"(a), "l"(b), "l"(c));
    return d;
}
union F4U2 { float4 f; ulonglong2 u; };

__device__ __forceinline__ void red_add_v4(float* p, float4 v) {
    asm volatile("red.global.add.v4.f32 [%0], {%1,%2,%3,%4};"
                 :: "l"(p), "f"(v.x), "f"(v.y), "f"(v.z), "f"(v.w)
                 : "memory");
}
__device__ __forceinline__ uint32_t smem_u32(const void* p) {
    uint32_t a;
    asm("{ .reg .u64 t; cvta.to.shared.u64 t, %1; cvt.u32.u64 %0, t; }"
        : "=r"(a) : "l"(p));
    return a;
}
__device__ __forceinline__ uint32_t bf2bits(__nv_bfloat162 h) {
    return *reinterpret_cast<uint32_t*>(&h);
}
__device__ __forceinline__ void cvt_hi_lo(float4 x, uint2& hi, uint2& lo) {
    __nv_bfloat162 h01 = __floats2bfloat162_rn(x.x, x.y);
    __nv_bfloat162 h23 = __floats2bfloat162_rn(x.z, x.w);
    float2 f01 = __bfloat1622float2(h01);
    float2 f23 = __bfloat1622float2(h23);
    __nv_bfloat162 l01 = __floats2bfloat162_rn(x.x - f01.x, x.y - f01.y);
    __nv_bfloat162 l23 = __floats2bfloat162_rn(x.z - f23.x, x.w - f23.y);
    hi = make_uint2(bf2bits(h01), bf2bits(h23));
    lo = make_uint2(bf2bits(l01), bf2bits(l23));
}

#define LDSM4(r, addr) \
    asm volatile("ldmatrix.sync.aligned.m8n8.x4.shared.b16 {%0,%1,%2,%3}, [%4];" \
        : "=r"((r)[0]), "=r"((r)[1]), "=r"((r)[2]), "=r"((r)[3]) : "r"(addr))
#define LDSM4T(r, addr) \
    asm volatile("ldmatrix.sync.aligned.m8n8.x4.trans.shared.b16 {%0,%1,%2,%3}, [%4];" \
        : "=r"((r)[0]), "=r"((r)[1]), "=r"((r)[2]), "=r"((r)[3]) : "r"(addr))
#define MMA16816(c, a, b0_, b1_) \
    asm volatile("mma.sync.aligned.m16n8k16.row.col.f32.bf16.bf16.f32 " \
        "{%0,%1,%2,%3}, {%4,%5,%6,%7}, {%8,%9}, {%0,%1,%2,%3};" \
        : "+f"((c)[0]), "+f"((c)[1]), "+f"((c)[2]), "+f"((c)[3]) \
        : "r"((a)[0]), "r"((a)[1]), "r"((a)[2]), "r"((a)[3]), "r"(b0_), "r"(b1_))

#define CPA16(s, g, sz) \
    asm volatile("cp.async.cg.shared.global [%0], [%1], 16, %2;" \
                 :: "r"(s), "l"(g), "r"(sz) : "memory")
#define CPA_COMMIT() asm volatile("cp.async.commit_group;" ::: "memory")
#define CPA_WAIT0()  asm volatile("cp.async.wait_group 0;" ::: "memory")

// ---------------------------------------------------------------------------
// Node stage, tensor-core + cp.async pipelined.
// 4 fused GEMM segments, 128x128 tiles, K=128, bf16x3 (hi/lo split).
// Next tile's raw fp32 X streams into a 64KB smem buffer via cp.async while
// the current tile's MMAs run; convert raw->bf16 hi/lo costs ~LDS+STS only.
// ---------------------------------------------------------------------------
#define NT_THREADS 512
#define XSTRIDE    272
#define NXHI 0
#define NXLO 34816
#define NWHI 69632
#define NWLO 104448
#define NRAW 139264
#define NBS  204800
#define NT_SMEM (NBS + 512)

__global__ __launch_bounds__(NT_THREADS, 1)
void node_tc_kernel(const float* __restrict__ Xu, const float* __restrict__ Xi,
                    const float* __restrict__ Wsu, const float* __restrict__ bu,
                    float* __restrict__ xwu,
                    const float* __restrict__ Wlu, const float* __restrict__ blu,
                    float* __restrict__ Hu,
                    const float* __restrict__ Wsi, const float* __restrict__ bi,
                    float* __restrict__ xwi,
                    const float* __restrict__ Wli, const float* __restrict__ bli,
                    float* __restrict__ Hi,
                    int nu, int ni)
{
    extern __shared__ char smem[];
    const uint32_t sbase = smem_u32(smem);
    float* bs = (float*)(smem + NBS);
    const float4* rawv = (const float4*)(smem + NRAW);

    const int tid  = threadIdx.x;
    const int warp = tid >> 5;
    const int lane = tid & 31;
    const int r0 = (warp >> 1) * 16;
    const int n0 = (warp & 1) * 64;

    const float* Xs_[4] = {Xu, Xu, Xi, Xi};
    const float* Ws_[4] = {Wsu, Wlu, Wsi, Wli};
    const float* bs_[4] = {bu, blu, bi, bli};
    float*       Ys_[4] = {xwu, Hu, xwi, Hi};
    const int    ns_[4] = {nu, nu, ni, ni};

    const int tu = (nu + 127) >> 7;
    const int ti = (ni + 127) >> 7;
    const int cum[5] = {0, tu, 2 * tu, 2 * tu + ti, 2 * tu + 2 * ti};
    const int total = cum[4];
    const int G = gridDim.x;

    const uint32_t a_off = (uint32_t)((r0 + (lane & 15)) * XSTRIDE + (lane >> 4) * 16);
    const int bg = lane >> 3;
    const uint32_t b_off = (uint32_t)(((lane & 7) + (bg & 1) * 8) * XSTRIDE
                                      + (n0 + (bg >> 1) * 8) * 2);

    // Issue the raw X copy for tile tt (async, no registers held).
    auto issue_copy = [&](int tt) {
        int seg = (tt >= cum[2]) ? ((tt >= cum[3]) ? 3 : 2)
                                 : ((tt >= cum[1]) ? 1 : 0);
        const float* Xg = Xs_[seg];
        const int n = ns_[seg];
        const int row_base = (tt - cum[seg]) * 128;
        #pragma unroll
        for (int j = 0; j < 8; j++) {
            int idx = tid + j * NT_THREADS;      // 4096 float4 chunks
            int row = idx >> 5, c4 = idx & 31;
            int grow = row_base + row;
            int ok = (grow < n);
            const float* src = Xg + (size_t)(ok ? grow : 0) * 128 + c4 * 4;
            CPA16(sbase + NRAW + idx * 16, src, ok ? 16 : 0);
        }
        CPA_COMMIT();
    };

    int cur_seg = -1;
    int t = blockIdx.x;
    if (t < total) issue_copy(t);

    for (; t < total; t += G) {
        int seg = (t >= cum[2]) ? ((t >= cum[3]) ? 3 : 2)
                                : ((t >= cum[1]) ? 1 : 0);
        const int n = ns_[seg];
        const int row_base = (t - cum[seg]) * 128;
        float* Y = Ys_[seg];

        if (seg != cur_seg) {
            __syncthreads();   // old W/X readers done
            const float4* Wg = (const float4*)Ws_[seg];
            #pragma unroll
            for (int j = 0; j < 8; j++) {
                int idx = tid + j * NT_THREADS;
                int row = idx >> 5, c4 = idx & 31;
                uint2 hi, lo;
                cvt_hi_lo(Wg[row * 32 + c4], hi, lo);
                *(uint2*)(smem + NWHI + row * XSTRIDE + c4 * 8) = hi;
                *(uint2*)(smem + NWLO + row * XSTRIDE + c4 * 8) = lo;
            }
            if (tid < 128) bs[tid] = bs_[seg][tid];
            cur_seg = seg;
        }

        CPA_WAIT0();           // raw X tile landed (long ago, usually)
        __syncthreads();       // + previous tile's hi/lo readers done

        // Convert raw fp32 -> bf16 hi/lo (each thread owns its own chunks).
        #pragma unroll
        for (int j = 0; j < 8; j++) {
            int idx = tid + j * NT_THREADS;
            int row = idx >> 5, c4 = idx & 31;
            uint2 hi, lo;
            cvt_hi_lo(rawv[idx], hi, lo);
            *(uint2*)(smem + NXHI + row * XSTRIDE + c4 * 8) = hi;
            *(uint2*)(smem + NXLO + row * XSTRIDE + c4 * 8) = lo;
        }
        __syncthreads();

        // Kick off next tile's raw copy; it streams under the MMA loop.
        if (t + G < total) issue_copy(t + G);

        float acc[8][4];
        #pragma unroll
        for (int i = 0; i < 8; i++)
            #pragma unroll
            for (int j = 0; j < 4; j++) acc[i][j] = 0.f;

        #pragma unroll
        for (int k0 = 0; k0 < 128; k0 += 16) {
            uint32_t ah[4], al[4];
            uint32_t aaddr = sbase + NXHI + a_off + k0 * 2;
            LDSM4(ah, aaddr);
            LDSM4(al, aaddr + (NXLO - NXHI));
            #pragma unroll
            for (int c = 0; c < 4; c++) {
                uint32_t bh[4], bl[4];
                uint32_t baddr = sbase + NWHI + b_off + k0 * XSTRIDE + c * 32;
                LDSM4T(bh, baddr);
                LDSM4T(bl, baddr + (NWLO - NWHI));
                MMA16816(acc[2 * c],     ah, bh[0], bh[1]);
                MMA16816(acc[2 * c + 1], ah, bh[2], bh[3]);
                MMA16816(acc[2 * c],     ah, bl[0], bl[1]);
                MMA16816(acc[2 * c + 1], ah, bl[2], bl[3]);
                MMA16816(acc[2 * c],     al, bh[0], bh[1]);
                MMA16816(acc[2 * c + 1], al, bh[2], bh[3]);
            }
        }

        const int ra = row_base + r0 + (lane >> 2);
        const int rb = ra + 8;
        #pragma unroll
        for (int c8 = 0; c8 < 8; c8++) {
            int col = n0 + c8 * 8 + 2 * (lane & 3);
            float b0 = bs[col], b1 = bs[col + 1];
            if (ra < n) {
                float2 v = make_float2(acc[c8][0] + b0, acc[c8][1] + b1);
                *(float2*)(Y + (size_t)ra * 128 + col) = v;
            }
            if (rb < n) {
                float2 v = make_float2(acc[c8][2] + b0, acc[c8][3] + b1);
                *(float2*)(Y + (size_t)rb * 128 + col) = v;
            }
        }
    }
}

// ---------------------------------------------------------------------------
// Relation kernel: R7 internals, both relations fused into one launch
// (blockIdx.y selects the pointer set) so the second relation fills the
// first one's tail.
// ---------------------------------------------------------------------------
#define REL_THREADS 256
#define REL_EPW 8
#define REL_TILE 64

__device__ __forceinline__ int rel_load_idx(const int* __restrict__ src,
                                            const int* __restrict__ dst,
                                            int ebase, int lane, int E) {
    if (lane < 8) {
        int e = ebase + lane;
        return (e < E) ? __ldg(src + e) : 0;
    } else if (lane < 16) {
        int e = ebase + lane - 8;
        return (e < E) ? __ldg(dst + e) : 0;
    }
    return 0;
}

__global__ __launch_bounds__(REL_THREADS, 2)
void rel_kernel(const float* __restrict__ XW0, const float* __restrict__ Xe0,
                const int* __restrict__ src0, const int* __restrict__ dst0,
                const float* __restrict__ We0, float* __restrict__ out0,
                const float* __restrict__ XW1, const float* __restrict__ Xe1,
                const int* __restrict__ src1, const int* __restrict__ dst1,
                const float* __restrict__ We1, float* __restrict__ out1,
                int E)
{
    const float* XW = blockIdx.y ? XW1 : XW0;
    const float* Xe = blockIdx.y ? Xe1 : Xe0;
    const int*  src = blockIdx.y ? src1 : src0;
    const int*  dst = blockIdx.y ? dst1 : dst0;
    const float* We = blockIdx.y ? We1 : We0;
    float*      out = blockIdx.y ? out1 : out0;

    __shared__ float Wes[D_EDGE * D_OUT];
    __shared__ float Xs[REL_TILE * D_EDGE];

    const int tid = threadIdx.x;
    {
        const float4* Weg = (const float4*)We;
        float4* Wesv = (float4*)Wes;
        #pragma unroll
        for (int i = tid; i < (D_EDGE * D_OUT) / 4; i += REL_THREADS)
            Wesv[i] = Weg[i];
    }

    const int warp = tid >> 5;
    const int lane = tid & 31;
    const int r0 = warp * REL_EPW;
    const ulonglong2* Wv = (const ulonglong2*)Wes;
    float4* Xsv = (float4*)Xs;
    const float4* Xeg = (const float4*)Xe;

    const int ntiles = (E + REL_TILE - 1) / REL_TILE;
    const int G = gridDim.x;
    const int nf4 = E * (D_EDGE / 4);

    int t = blockIdx.x;

    int idx_cur  = rel_load_idx(src, dst, t * REL_TILE + warp * 8, lane, E);
    int idx_next = rel_load_idx(src, dst, (t + G) * REL_TILE + warp * 8, lane, E);

    F4U2 gc[REL_EPW];
    #pragma unroll
    for (int r = 0; r < REL_EPW; r++) {
        int s = __shfl_sync(0xffffffffu, idx_cur, r);
        gc[r].f = __ldg((const float4*)(XW + (size_t)s * 128) + lane);
    }

    float4 pa = make_float4(0.f, 0.f, 0.f, 0.f);
    float4 pb = pa;
    if (t < ntiles) {
        int i0 = t * (REL_TILE * D_EDGE / 4) + tid;
        int i1 = i0 + REL_THREADS;
        if (i0 < nf4) pa = Xeg[i0];
        if (i1 < nf4) pb = Xeg[i1];
    }
    __syncthreads();
    if (t < ntiles) { Xsv[tid] = pa; Xsv[tid + REL_THREADS] = pb; }
    __syncthreads();

    for (; t < ntiles; t += G) {
        const int tn = t + G;
        const int e0 = t * REL_TILE;

        F4U2 gn[REL_EPW];
        #pragma unroll
        for (int r = 0; r < REL_EPW; r++) {
            int s = __shfl_sync(0xffffffffu, idx_next, r);
            gn[r].f = __ldg((const float4*)(XW + (size_t)s * 128) + lane);
        }
        int idx_n2 = rel_load_idx(src, dst, (t + 2 * G) * REL_TILE + warp * 8, lane, E);
        if (tn < ntiles) {
            int i0 = tn * (REL_TILE * D_EDGE / 4) + tid;
            int i1 = i0 + REL_THREADS;
            pa = (i0 < nf4) ? Xeg[i0] : make_float4(0.f, 0.f, 0.f, 0.f);
            pb = (i1 < nf4) ? Xeg[i1] : make_float4(0.f, 0.f, 0.f, 0.f);
        }

        ulonglong2 acc[REL_EPW];
        #pragma unroll
        for (int r = 0; r < REL_EPW; r++) acc[r] = gc[r].u;

        #pragma unroll
        for (int k4 = 0; k4 < D_EDGE / 4; k4++) {
            const int k0 = 4 * k4;
            ulonglong2 w0 = Wv[(k0 + 0) * 32 + lane];
            ulonglong2 w1 = Wv[(k0 + 1) * 32 + lane];
            ulonglong2 w2 = Wv[(k0 + 2) * 32 + lane];
            ulonglong2 w3 = Wv[(k0 + 3) * 32 + lane];
            #pragma unroll
            for (int r = 0; r < REL_EPW; r++) {
                float4 xv = *(const float4*)&Xs[(r0 + r) * D_EDGE + k0];
                unsigned long long xa = pk2(xv.x);
                unsigned long long xb = pk2(xv.y);
                unsigned long long xc = pk2(xv.z);
                unsigned long long xd = pk2(xv.w);
                acc[r].x = fma2(xa, w0.x, acc[r].x);
                acc[r].y = fma2(xa, w0.y, acc[r].y);
                acc[r].x = fma2(xb, w1.x, acc[r].x);
                acc[r].y = fma2(xb, w1.y, acc[r].y);
                acc[r].x = fma2(xc, w2.x, acc[r].x);
                acc[r].y = fma2(xc, w2.y, acc[r].y);
                acc[r].x = fma2(xd, w3.x, acc[r].x);
                acc[r].y = fma2(xd, w3.y, acc[r].y);
            }
        }

        #pragma unroll
        for (int r = 0; r < REL_EPW; r++) {
            if (e0 + r0 + r < E) {
                int d = __shfl_sync(0xffffffffu, idx_cur, r + 8);
                F4U2 o; o.u = acc[r];
                float4 v = o.f;
                v.x = fmaxf(v.x, 0.f); v.y = fmaxf(v.y, 0.f);
                v.z = fmaxf(v.z, 0.f); v.w = fmaxf(v.w, 0.f);
                red_add_v4(out + (size_t)d * 128 + 4 * lane, v);
            }
        }

        __syncthreads();
        if (tn < ntiles) { Xsv[tid] = pa; Xsv[tid + REL_THREADS] = pb; }
        __syncthreads();

        #pragma unroll
        for (int r = 0; r < REL_EPW; r++) gc[r] = gn[r];
        idx_cur = idx_next;
        idx_next = idx_n2;
    }
}

// ---------------------------------------------------------------------------
// kernel_launch (metadata order unchanged)
// ---------------------------------------------------------------------------
extern "C" void kernel_launch(void* const* d_in, const int* in_sizes, int n_in,
                              void* d_out, int out_size)
{
    const float* X_user   = (const float*)d_in[0];
    const float* X_item   = (const float*)d_in[1];
    const float* Xe_ui    = (const float*)d_in[2];
    const float* Xe_iu    = (const float*)d_in[3];
    const float* W_src_ui = (const float*)d_in[4];
    const float* W_edge_ui= (const float*)d_in[5];
    const float* b_ui     = (const float*)d_in[6];
    const float* W_src_iu = (const float*)d_in[7];
    const float* W_edge_iu= (const float*)d_in[8];
    const float* b_iu     = (const float*)d_in[9];
    const float* Wl_user  = (const float*)d_in[10];
    const float* bl_user  = (const float*)d_in[11];
    const float* Wl_item  = (const float*)d_in[12];
    const float* bl_item  = (const float*)d_in[13];
    const int*   src_ui   = (const int*)d_in[14];
    const int*   dst_ui   = (const int*)d_in[15];
    const int*   src_iu   = (const int*)d_in[16];
    const int*   dst_iu   = (const int*)d_in[17];

    const int n_user = in_sizes[0] / D_IN;
    const int n_item = in_sizes[1] / D_IN;
    const int E      = in_sizes[14];

    float* H_user = (float*)d_out;
    float* H_item = (float*)d_out + (size_t)n_user * D_OUT;

    void* p_xwu = nullptr; void* p_xwi = nullptr;
    cudaGetSymbolAddress(&p_xwu, g_xwu);
    cudaGetSymbolAddress(&p_xwi, g_xwi);
    float* xwu = (float*)p_xwu;
    float* xwi = (float*)p_xwi;

    cudaFuncSetAttribute(node_tc_kernel,
                         cudaFuncAttributeMaxDynamicSharedMemorySize,
                         NT_SMEM);

    node_tc_kernel<<<148, NT_THREADS, NT_SMEM>>>(
        X_user, X_item,
        W_src_ui, b_ui, xwu,
        Wl_user, bl_user, H_user,
        W_src_iu, b_iu, xwi,
        Wl_item, bl_item, H_item,
        n_user, n_item);

    dim3 grel(296, 2);
    rel_kernel<<<grel, REL_THREADS>>>(
        xwu, Xe_ui, src_ui, dst_ui, W_edge_ui, H_item,
        xwi, Xe_iu, src_iu, dst_iu, W_edge_iu, H_user,
        E);
}